// round 16
// baseline (speedup 1.0000x reference)
#include <cuda_runtime.h>
#include <cuda_fp16.h>
#include <math.h>
#include <stdint.h>

#define B_    2
#define S_    2048
#define HID_  512
#define H_    8
#define BH_   16
#define M_    4096

// Scratch (device globals; no allocation allowed)
__device__ __align__(256) __half g_Qh[M_ * HID_];
__device__ __align__(256) __half g_Kh[M_ * HID_];
__device__ __align__(256) __half g_Vh[M_ * HID_];
__device__ __align__(256) __half g_Vt[BH_ * 64 * S_];   // [z][d][s]
__device__ __align__(256) __half g_Xh[M_ * HID_];
__device__ __align__(256) __half g_Wh[4 * HID_ * HID_]; // fp16 Wq,Wk,Wv,Wo
__device__ __align__(256) __half g_inx[3 * M_ * HID_];  // fp16 q,k,v inputs
__device__ float g_rowinv[BH_ * S_];
__device__ uint32_t g_pm[M_ * 64];                      // packed mask bits, 1MB
__device__ float g_attn_scratch[(size_t)BH_ * S_ * S_];

// ---------------------------------------------------------------------------
// helpers
// ---------------------------------------------------------------------------
__device__ __forceinline__ unsigned f2h2(float a, float b) {
    __half2 h = __floats2half2_rn(a, b);
    return *(unsigned*)&h;
}

__device__ __forceinline__ float ex2f(float x) {
    float y;
    asm("ex2.approx.f32 %0, %1;" : "=f"(y) : "f"(x));
    return y;
}

__device__ __forceinline__ void mmah(float c[4], const unsigned a[4], const unsigned b[2]) {
    asm volatile(
        "mma.sync.aligned.m16n8k16.row.col.f32.f16.f16.f32 "
        "{%0,%1,%2,%3},{%4,%5,%6,%7},{%8,%9},{%0,%1,%2,%3};"
        : "+f"(c[0]), "+f"(c[1]), "+f"(c[2]), "+f"(c[3])
        : "r"(a[0]), "r"(a[1]), "r"(a[2]), "r"(a[3]),
          "r"(b[0]), "r"(b[1]));
}

__device__ __forceinline__ void ldsm4(uint32_t& r0, uint32_t& r1, uint32_t& r2,
                                      uint32_t& r3, uint32_t a) {
    asm volatile("ldmatrix.sync.aligned.m8n8.x4.shared.b16 {%0,%1,%2,%3}, [%4];"
                 : "=r"(r0), "=r"(r1), "=r"(r2), "=r"(r3) : "r"(a));
}

__device__ __forceinline__ void cp16(uint32_t saddr, const void* g) {
    asm volatile("cp.async.cg.shared.global [%0], [%1], 16;" :: "r"(saddr), "l"(g));
}
__device__ __forceinline__ uint32_t sptr(const void* p) {
    return (uint32_t)__cvta_generic_to_shared(p);
}
__device__ __forceinline__ void stg_cs2(float* p, float a, float b) {
    asm volatile("st.global.cs.v2.f32 [%0], {%1,%2};" :: "l"(p), "f"(a), "f"(b));
}

// ---------------------------------------------------------------------------
// Fused one-time converts: inputs fp32->fp16, mask bit-pack, weights fp32->fp16.
// ---------------------------------------------------------------------------
__global__ void __launch_bounds__(256)
xcvt(const float* __restrict__ q, const float* __restrict__ k,
     const float* __restrict__ v, __half* __restrict__ dst,
     const int* __restrict__ mask, uint32_t* __restrict__ pm,
     const float* __restrict__ Wq, const float* __restrict__ Wk,
     const float* __restrict__ Wv, const float* __restrict__ Wo,
     __half* __restrict__ Wh)
{
    if (blockIdx.x >= 6144) {
        int idx = ((blockIdx.x - 6144) * 256 + threadIdx.x) * 4;
        const float* s = (idx < 262144) ? Wq
                       : (idx < 524288) ? Wk
                       : (idx < 786432) ? Wv : Wo;
        float4 w = *(const float4*)(s + (idx & 262143));
        __half2 h0 = __floats2half2_rn(w.x, w.y);
        __half2 h1 = __floats2half2_rn(w.z, w.w);
        *(uint2*)(Wh + idx) = make_uint2(*(unsigned*)&h0, *(unsigned*)&h1);
        return;
    }

    if (blockIdx.x < 1024) {
        int widx = blockIdx.x * 256 + threadIdx.x;
        const int4* mp = (const int4*)(mask + (size_t)widx * 32);
        uint32_t u = 0;
        #pragma unroll
        for (int j = 0; j < 8; j++) {
            int4 m = __ldg(mp + j);
            u |= (m.x != 0 ? 1u : 0u) << (j * 4);
            u |= (m.y != 0 ? 1u : 0u) << (j * 4 + 1);
            u |= (m.z != 0 ? 1u : 0u) << (j * 4 + 2);
            u |= (m.w != 0 ? 1u : 0u) << (j * 4 + 3);
        }
        pm[widx] = u;
    }

    int idx = (blockIdx.x * 256 + threadIdx.x) * 4;
    const float* s = (idx < 2097152) ? q : (idx < 4194304) ? k : v;
    float4 w = *(const float4*)(s + (idx & 2097151));
    __half2 h0 = __floats2half2_rn(w.x, w.y);
    __half2 h1 = __floats2half2_rn(w.z, w.w);
    *(uint2*)(dst + idx) = make_uint2(*(unsigned*)&h0, *(unsigned*)&h1);
}

// ---------------------------------------------------------------------------
// Unified projection (fp16 X, fp16 W): Y = (X @ W^T + b) * scale
// ---------------------------------------------------------------------------
struct ProjArgs { const __half* X; const __half* W; const float* b;
                  __half* Yh; float* Yf; float scale; };

#define PJ_STAGE 15360
#define PJ_X(s) ((s) * PJ_STAGE)
#define PJ_W(s) ((s) * PJ_STAGE + 10240)
#define PJ_SMEM (3 * PJ_STAGE)

__global__ void __launch_bounds__(256, 3)
proj_h(ProjArgs a0, ProjArgs a1, ProjArgs a2)
{
    const ProjArgs& A_ = (blockIdx.z == 0) ? a0 : (blockIdx.z == 1) ? a1 : a2;
    const __half* __restrict__ Xg = A_.X;
    const __half* __restrict__ Wg = A_.W;
    const float* __restrict__ bias = A_.b;

    extern __shared__ char psm[];
    const uint32_t sb = sptr(psm);

    const int tid = threadIdx.x;
    const int lane = tid & 31, wid = tid >> 5;
    const int g = lane >> 2, tg = lane & 3;
    const int wm = wid & 3, wn = wid >> 2;
    const int m0 = blockIdx.y * 128, n0 = blockIdx.x * 64;

    auto stage = [&](int k0, int s) {
        #pragma unroll
        for (int j = 0; j < 2; j++) {
            int lin = tid + j * 256;
            int r = lin >> 2, c16 = lin & 3;
            cp16(sb + PJ_X(s) + (uint32_t)r * 80u + (uint32_t)c16 * 16u,
                 Xg + (size_t)(m0 + r) * 512 + k0 + c16 * 8);
        }
        {
            int r = tid >> 2, c16 = tid & 3;
            cp16(sb + PJ_W(s) + (uint32_t)r * 80u + (uint32_t)c16 * 16u,
                 Wg + (size_t)(n0 + r) * 512 + k0 + c16 * 8);
        }
        asm volatile("cp.async.commit_group;");
    };

    float acc[2][4][4] = {};

    stage(0, 0);
    stage(32, 1);
    for (int t = 0; t < 16; t++) {
        if (t < 15) asm volatile("cp.async.wait_group 1;");
        else        asm volatile("cp.async.wait_group 0;");
        __syncthreads();
        if (t + 2 < 16) stage((t + 2) * 32, (t + 2) % 3);

        const __half* Xs = (const __half*)(psm + PJ_X(t % 3));
        const __half* Ws = (const __half*)(psm + PJ_W(t % 3));

        #pragma unroll
        for (int ks = 0; ks < 2; ks++) {
            unsigned af[2][4], bf[4][2];
            #pragma unroll
            for (int mi = 0; mi < 2; mi++) {
                const __half* x0 = &Xs[(wm * 32 + mi * 16 + g) * 40 + ks * 16 + 2 * tg];
                const __half* x1 = x0 + 8 * 40;
                af[mi][0] = *(const uint32_t*)x0;
                af[mi][1] = *(const uint32_t*)x1;
                af[mi][2] = *(const uint32_t*)(x0 + 8);
                af[mi][3] = *(const uint32_t*)(x1 + 8);
            }
            #pragma unroll
            for (int ni = 0; ni < 4; ni++) {
                const __half* bb = &Ws[(wn * 32 + ni * 8 + g) * 40 + ks * 16 + 2 * tg];
                bf[ni][0] = *(const uint32_t*)bb;
                bf[ni][1] = *(const uint32_t*)(bb + 8);
            }
            #pragma unroll
            for (int mi = 0; mi < 2; mi++)
                #pragma unroll
                for (int ni = 0; ni < 4; ni++)
                    mmah(acc[mi][ni], af[mi], bf[ni]);
        }
    }

    const float scale = A_.scale;
    #pragma unroll
    for (int mi = 0; mi < 2; mi++) {
        int r0 = m0 + wm * 32 + mi * 16 + g;
        #pragma unroll
        for (int ni = 0; ni < 4; ni++) {
            int c0 = n0 + wn * 32 + ni * 8 + 2 * tg;
            float b0v = __ldg(bias + c0), b1v = __ldg(bias + c0 + 1);
            float y00 = acc[mi][ni][0] + b0v, y01 = acc[mi][ni][1] + b1v;
            float y10 = acc[mi][ni][2] + b0v, y11 = acc[mi][ni][3] + b1v;
            if (A_.Yh) {
                *(unsigned*)(A_.Yh + (size_t)r0 * 512 + c0) = f2h2(y00 * scale, y01 * scale);
                *(unsigned*)(A_.Yh + (size_t)(r0 + 8) * 512 + c0) = f2h2(y10 * scale, y11 * scale);
            } else {
                *(float2*)(A_.Yf + (size_t)r0 * 512 + c0) = make_float2(y00, y01);
                *(float2*)(A_.Yf + (size_t)(r0 + 8) * 512 + c0) = make_float2(y10, y11);
            }
        }
    }
}

// ---------------------------------------------------------------------------
// vtrans: Vh [b,s,hid] -> Vt [z][d][s]
// ---------------------------------------------------------------------------
__global__ void __launch_bounds__(256)
vtrans(const __half* __restrict__ Vh, __half* __restrict__ Vt)
{
    __shared__ __half ts[64 * 72];
    const int tid = threadIdx.x;
    const int z = blockIdx.y, bB = z >> 3, h = z & 7;
    const int s0 = blockIdx.x * 64;

    #pragma unroll
    for (int j = 0; j < 8; j++) {
        int lin = tid + j * 256;
        int s = lin >> 5, du = lin & 31;
        *(uint32_t*)(ts + s * 72 + du * 2) =
            *(const uint32_t*)(Vh + (size_t)(bB * S_ + s0 + s) * HID_ + h * 64 + du * 2);
    }
    __syncthreads();
    #pragma unroll
    for (int j = 0; j < 8; j++) {
        int lin = tid + j * 256;
        int d = lin >> 5, su = lin & 31;
        __half2 o = __halves2half2(ts[(2 * su) * 72 + d], ts[(2 * su + 1) * 72 + d]);
        *(__half2*)(Vt + ((size_t)z * 64 + d) * S_ + s0 + su * 2) = o;
    }
}

// ---------------------------------------------------------------------------
// attn_A: 8 x 256-col chunks, 2-stage ring (1 barrier per chunk).
// scores+ex2 -> rowsum + PV (register P). Outputs rowinv + Xh.
// ---------------------------------------------------------------------------
#define SMA_Q    0u
#define SMA_K(s) (9216u + (s) * 36864u)
#define SMA_V(s) (82944u + (s) * 33792u)
#define SMA_RS   150528u
#define ATTN_SMEM (150784 + 16)

__global__ void __launch_bounds__(512, 1)
attn_A(const __half* __restrict__ Qh, const __half* __restrict__ Kh,
       const __half* __restrict__ Vtg, const uint32_t* __restrict__ pm,
       float* __restrict__ rowinv, __half* __restrict__ Xo)
{
    extern __shared__ char smg[];
    const uint32_t sb = sptr(smg);

    const int tid = threadIdx.x, lane = tid & 31, w = tid >> 5;
    const int g = lane >> 2, tg = lane & 3;
    const int wm = w & 3, wn = w >> 2;
    const int z = blockIdx.y, strip = blockIdx.x;
    const int bB = z >> 3, h = z & 7;
    const int s0 = strip * 64;

    float* rows = (float*)(smg + SMA_RS);
    if (tid < 64) rows[tid] = 0.f;

    const __half* Qsrc = Qh + (size_t)(bB * S_ + s0) * HID_ + h * 64;
    const __half* Ksrc = Kh + (size_t)(bB * S_) * HID_ + h * 64;
    const __half* Vsrc = Vtg + (size_t)z * 64 * S_;

    // ldmatrix lane offsets (bytes) within a 128-col half
    const uint32_t so_sc = (uint32_t)(wn * 32 + (lane & 7)) * 144u
                         + ((lane >> 4) & 1) * 32u + ((lane >> 3) & 1) * 16u;
    const uint32_t so_pv = (uint32_t)(lane & 7) * 528u + (uint32_t)wn * 64u
                         + ((lane >> 4) & 1) * 32u + ((lane >> 3) & 1) * 16u;

    auto loadKV = [&](int chunk, int st) {
        const int kb = chunk * 256;
        #pragma unroll
        for (int j = 0; j < 4; j++) {
            int idx = tid + j * 512;
            int r = idx >> 3, c16 = idx & 7;
            cp16(sb + SMA_K(st) + (uint32_t)r * 144u + (uint32_t)c16 * 16u,
                 Ksrc + (size_t)(kb + r) * HID_ + c16 * 8);
        }
        #pragma unroll
        for (int j = 0; j < 4; j++) {
            int idx = tid + j * 512;
            int d = idx >> 5, c16 = idx & 31;
            cp16(sb + SMA_V(st) + (uint32_t)d * 528u + (uint32_t)c16 * 16u,
                 Vsrc + (size_t)d * S_ + kb + c16 * 8);
        }
        asm volatile("cp.async.commit_group;");
    };

    {
        int r = tid >> 3, c16 = tid & 7;
        cp16(sb + SMA_Q + (uint32_t)r * 144u + (uint32_t)c16 * 16u,
             Qsrc + (size_t)r * HID_ + c16 * 8);
    }
    loadKV(0, 0);

    // Q frags after chunk0+Q complete
    asm volatile("cp.async.wait_group 0;");
    __syncthreads();

    const __half* Qs = (const __half*)(smg + SMA_Q);
    unsigned qa[4][4];
    #pragma unroll
    for (int ks = 0; ks < 4; ks++) {
        const __half* qr0 = Qs + (wm * 16 + g) * 72 + ks * 16 + 2 * tg;
        const __half* qr1 = qr0 + 8 * 72;
        qa[ks][0] = *(const uint32_t*)qr0;
        qa[ks][1] = *(const uint32_t*)qr1;
        qa[ks][2] = *(const uint32_t*)(qr0 + 8);
        qa[ks][3] = *(const uint32_t*)(qr1 + 8);
    }

    float pvacc[8][4] = {};
    float rsA = 0.f, rsB = 0.f;

    const int rA = bB * S_ + s0 + wm * 16 + g;

    for (int it = 0; it < 8; it++) {
        const int st = it & 1;

        if (it > 0) {
            asm volatile("cp.async.wait_group 0;");  // chunk it ready
            __syncthreads();                          // also frees buf st for next issue
        }
        if (it + 1 < 8) loadKV(it + 1, st ^ 1);

        #pragma unroll 1
        for (int hf = 0; hf < 2; hf++) {
            const uint32_t hoff = (uint32_t)hf * 128u;

            const uint32_t wa = __ldg(pm + (uint32_t)rA * 64u + it * 8 + hf * 4 + wn);
            const uint32_t wb = __ldg(pm + (uint32_t)(rA + 8) * 64u + it * 8 + hf * 4 + wn);

            float c[4][4] = {};
            {
                const uint32_t kbase = sb + SMA_K(st) + hoff * 144u + so_sc;
                #pragma unroll
                for (int p = 0; p < 2; p++) {
                    #pragma unroll
                    for (int nt = 0; nt < 4; nt++) {
                        uint32_t r0, r1, r2, r3;
                        ldsm4(r0, r1, r2, r3, kbase + (uint32_t)nt * 1152u + (uint32_t)p * 64u);
                        unsigned b0[2] = { r0, r1 }, b1[2] = { r2, r3 };
                        mmah(c[nt], qa[2 * p], b0);
                        mmah(c[nt], qa[2 * p + 1], b1);
                    }
                }
            }

            float p[4][4];
            #pragma unroll
            for (int nt = 0; nt < 4; nt++) {
                p[nt][0] = ex2f(c[nt][0]);
                p[nt][1] = ex2f(c[nt][1]);
                p[nt][2] = ex2f(c[nt][2]);
                p[nt][3] = ex2f(c[nt][3]);
            }
            if ((wa & wb) != 0xFFFFFFFFu) {
                #pragma unroll
                for (int nt = 0; nt < 4; nt++) {
                    int sh = nt * 8 + 2 * tg;
                    if (!((wa >> sh) & 1u))       p[nt][0] = 0.f;
                    if (!((wa >> (sh + 1)) & 1u)) p[nt][1] = 0.f;
                    if (!((wb >> sh) & 1u))       p[nt][2] = 0.f;
                    if (!((wb >> (sh + 1)) & 1u)) p[nt][3] = 0.f;
                }
            }
            #pragma unroll
            for (int nt = 0; nt < 4; nt++) {
                rsA += p[nt][0] + p[nt][1];
                rsB += p[nt][2] + p[nt][3];
            }

            unsigned pa[2][4];
            #pragma unroll
            for (int k2 = 0; k2 < 2; k2++) {
                pa[k2][0] = f2h2(p[2 * k2][0], p[2 * k2][1]);
                pa[k2][1] = f2h2(p[2 * k2][2], p[2 * k2][3]);
                pa[k2][2] = f2h2(p[2 * k2 + 1][0], p[2 * k2 + 1][1]);
                pa[k2][3] = f2h2(p[2 * k2 + 1][2], p[2 * k2 + 1][3]);
            }

            {
                const uint32_t vbase = sb + SMA_V(st) + hoff * 2u + so_pv;
                #pragma unroll
                for (int nt2 = 0; nt2 < 8; nt2++) {
                    uint32_t r0, r1, r2, r3;
                    ldsm4(r0, r1, r2, r3, vbase + (uint32_t)nt2 * 4224u);
                    unsigned b0[2] = { r0, r1 }, b1[2] = { r2, r3 };
                    mmah(pvacc[nt2], pa[0], b0);
                    mmah(pvacc[nt2], pa[1], b1);
                }
            }
        }
    }

    rsA += __shfl_xor_sync(0xffffffffu, rsA, 1);
    rsA += __shfl_xor_sync(0xffffffffu, rsA, 2);
    rsB += __shfl_xor_sync(0xffffffffu, rsB, 1);
    rsB += __shfl_xor_sync(0xffffffffu, rsB, 2);
    if (tg == 0) {
        atomicAdd(&rows[wm * 16 + g    ], rsA);
        atomicAdd(&rows[wm * 16 + g + 8], rsB);
    }
    __syncthreads();

    if (tid < 64) {
        float inv = 1.0f / rows[tid];
        rows[tid] = inv;
        rowinv[(size_t)z * S_ + s0 + tid] = inv;
    }

    // PV cross-warp reduction: 4 disjoint 16KB areas inside K stages
    const uint32_t scrOff[4] = { SMA_K(0), SMA_K(0) + 16384u,
                                 SMA_K(1), SMA_K(1) + 16384u };
    {
        float* sw = (float*)(smg + scrOff[wn]);
        #pragma unroll
        for (int nt2 = 0; nt2 < 8; nt2++) {
            int col = nt2 * 8 + 2 * tg;
            *(float2*)&sw[(wm * 16 + g    ) * 64 + col] =
                make_float2(pvacc[nt2][0], pvacc[nt2][1]);
            *(float2*)&sw[(wm * 16 + g + 8) * 64 + col] =
                make_float2(pvacc[nt2][2], pvacc[nt2][3]);
        }
    }
    __syncthreads();

    {
        int r = tid >> 3, cg = (tid & 7) * 8;
        float4 s0v = make_float4(0, 0, 0, 0), s1v = make_float4(0, 0, 0, 0);
        #pragma unroll
        for (int ww = 0; ww < 4; ww++) {
            const float* sw = (const float*)(smg + scrOff[ww]);
            float4 u0 = *(const float4*)&sw[r * 64 + cg];
            float4 u1 = *(const float4*)&sw[r * 64 + cg + 4];
            s0v.x += u0.x; s0v.y += u0.y; s0v.z += u0.z; s0v.w += u0.w;
            s1v.x += u1.x; s1v.y += u1.y; s1v.z += u1.z; s1v.w += u1.w;
        }
        float inv = rows[r];
        uint4 ov;
        ov.x = f2h2(s0v.x * inv, s0v.y * inv);
        ov.y = f2h2(s0v.z * inv, s0v.w * inv);
        ov.z = f2h2(s1v.x * inv, s1v.y * inv);
        ov.w = f2h2(s1v.z * inv, s1v.w * inv);
        *(uint4*)(Xo + (size_t)(bB * S_ + s0 + r) * HID_ + h * 64 + cg) = ov;
    }
}

// ---------------------------------------------------------------------------
// attn_B: 8 x 256-col chunks, 2-stage K ring, ex2, pm fast path,
// evict-first attn stores. 64-row q-tile, 512 thr, 2 CTAs/SM.
// ---------------------------------------------------------------------------
#define BB_Q    0u
#define BB_K(s) (9216u + (s) * 36864u)
#define ATTNB_SMEM (9216 + 2 * 36864 + 16)

__global__ void __launch_bounds__(512, 2)
attn_B(const __half* __restrict__ Qh, const __half* __restrict__ Kh,
       const uint32_t* __restrict__ pm, const float* __restrict__ rowinv,
       float* __restrict__ attn)
{
    extern __shared__ char smg[];
    const uint32_t sb = sptr(smg);

    const int tid = threadIdx.x, lane = tid & 31, w = tid >> 5;
    const int g = lane >> 2, tg = lane & 3;
    const int wm = w & 3, wn = w >> 2;
    const int z = blockIdx.y, strip = blockIdx.x;
    const int bB = z >> 3, h = z & 7;
    const int s0 = strip * 64;

    const __half* Qsrc = Qh + (size_t)(bB * S_ + s0) * HID_ + h * 64;
    const __half* Ksrc = Kh + (size_t)(bB * S_) * HID_ + h * 64;

    const uint32_t so_sc = (uint32_t)(wn * 32 + (lane & 7)) * 144u
                         + ((lane >> 4) & 1) * 32u + ((lane >> 3) & 1) * 16u;

    auto loadK = [&](int chunk, int st) {
        const int kb = chunk * 256;
        #pragma unroll
        for (int j = 0; j < 4; j++) {
            int idx = tid + j * 512;
            int r = idx >> 3, c16 = idx & 7;
            cp16(sb + BB_K(st) + (uint32_t)r * 144u + (uint32_t)c16 * 16u,
                 Ksrc + (size_t)(kb + r) * HID_ + c16 * 8);
        }
        asm volatile("cp.async.commit_group;");
    };

    {
        int r = tid >> 3, c16 = tid & 7;
        cp16(sb + BB_Q + (uint32_t)r * 144u + (uint32_t)c16 * 16u,
             Qsrc + (size_t)r * HID_ + c16 * 8);
    }
    loadK(0, 0);
    asm volatile("cp.async.wait_group 0;");
    __syncthreads();

    const __half* Qs = (const __half*)(smg + BB_Q);
    unsigned qa[4][4];
    #pragma unroll
    for (int ks = 0; ks < 4; ks++) {
        const __half* qr0 = Qs + (wm * 16 + g) * 72 + ks * 16 + 2 * tg;
        const __half* qr1 = qr0 + 8 * 72;
        qa[ks][0] = *(const uint32_t*)qr0;
        qa[ks][1] = *(const uint32_t*)qr1;
        qa[ks][2] = *(const uint32_t*)(qr0 + 8);
        qa[ks][3] = *(const uint32_t*)(qr1 + 8);
    }

    const int rowA = s0 + wm * 16 + g;
    const int rA = bB * S_ + rowA;
    const float invA = __ldg(rowinv + (size_t)z * S_ + rowA);
    const float invB = __ldg(rowinv + (size_t)z * S_ + rowA + 8);
    const size_t arowA = ((size_t)z * S_ + rowA) * S_;
    const size_t arowB = arowA + 8 * S_;

    for (int it = 0; it < 8; it++) {
        const int st = it & 1;

        if (it > 0) {
            asm volatile("cp.async.wait_group 0;");
            __syncthreads();
        }
        if (it + 1 < 8) loadK(it + 1, st ^ 1);

        #pragma unroll 1
        for (int hf = 0; hf < 2; hf++) {
            const uint32_t hoff = (uint32_t)hf * 128u;
            const int kb = it * 256 + hf * 128;

            const uint32_t wa = __ldg(pm + (uint32_t)rA * 64u + it * 8 + hf * 4 + wn);
            const uint32_t wb = __ldg(pm + (uint32_t)(rA + 8) * 64u + it * 8 + hf * 4 + wn);

            float c[4][4] = {};
            {
                const uint32_t kbase = sb + BB_K(st) + hoff * 144u + so_sc;
                #pragma unroll
                for (int p = 0; p < 2; p++) {
                    #pragma unroll
                    for (int nt = 0; nt < 4; nt++) {
                        uint32_t r0, r1, r2, r3;
                        ldsm4(r0, r1, r2, r3, kbase + (uint32_t)nt * 1152u + (uint32_t)p * 64u);
                        unsigned b0[2] = { r0, r1 }, b1[2] = { r2, r3 };
                        mmah(c[nt], qa[2 * p], b0);
                        mmah(c[nt], qa[2 * p + 1], b1);
                    }
                }
            }

            float p[4][4];
            #pragma unroll
            for (int nt = 0; nt < 4; nt++) {
                p[nt][0] = ex2f(c[nt][0]) * invA;
                p[nt][1] = ex2f(c[nt][1]) * invA;
                p[nt][2] = ex2f(c[nt][2]) * invB;
                p[nt][3] = ex2f(c[nt][3]) * invB;
            }
            if ((wa & wb) != 0xFFFFFFFFu) {
                #pragma unroll
                for (int nt = 0; nt < 4; nt++) {
                    int sh = nt * 8 + 2 * tg;
                    if (!((wa >> sh) & 1u))       p[nt][0] = 0.f;
                    if (!((wa >> (sh + 1)) & 1u)) p[nt][1] = 0.f;
                    if (!((wb >> sh) & 1u))       p[nt][2] = 0.f;
                    if (!((wb >> (sh + 1)) & 1u)) p[nt][3] = 0.f;
                }
            }
            #pragma unroll
            for (int nt = 0; nt < 4; nt++) {
                int cg = kb + wn * 32 + nt * 8 + 2 * tg;
                stg_cs2(attn + arowA + cg, p[nt][0], p[nt][1]);
                stg_cs2(attn + arowB + cg, p[nt][2], p[nt][3]);
            }
        }
    }
}

// ---------------------------------------------------------------------------
// Launch
// ---------------------------------------------------------------------------
extern "C" void kernel_launch(void* const* d_in, const int* in_sizes, int n_in,
                              void* d_out, int out_size)
{
    const float* q    = (const float*)d_in[0];
    const float* k    = (const float*)d_in[1];
    const float* v    = (const float*)d_in[2];
    const int*   mask = (const int*)  d_in[3];
    const float* Wq   = (const float*)d_in[4];
    const float* bq   = (const float*)d_in[5];
    const float* Wk   = (const float*)d_in[6];
    const float* bk   = (const float*)d_in[7];
    const float* Wv   = (const float*)d_in[8];
    const float* bv   = (const float*)d_in[9];
    const float* Wo   = (const float*)d_in[10];
    const float* bo   = (const float*)d_in[11];

    float* out = (float*)d_out;

    __half *Qhp, *Khp, *Vhp, *Vtp, *Xhp, *Whp, *Xin;
    float *rinv, *scr;
    uint32_t* pmp;
    cudaGetSymbolAddress((void**)&Qhp, g_Qh);
    cudaGetSymbolAddress((void**)&Khp, g_Kh);
    cudaGetSymbolAddress((void**)&Vhp, g_Vh);
    cudaGetSymbolAddress((void**)&Vtp, g_Vt);
    cudaGetSymbolAddress((void**)&Xhp, g_Xh);
    cudaGetSymbolAddress((void**)&Whp, g_Wh);
    cudaGetSymbolAddress((void**)&Xin, g_inx);
    cudaGetSymbolAddress((void**)&rinv, g_rowinv);
    cudaGetSymbolAddress((void**)&pmp, g_pm);
    cudaGetSymbolAddress((void**)&scr, g_attn_scratch);

    const size_t out_elems  = (size_t)M_ * HID_;
    const size_t attn_elems = (size_t)BH_ * S_ * S_;
    float* attn = ((size_t)out_size >= out_elems + attn_elems) ? out + out_elems : scr;

    cudaFuncSetAttribute(attn_A, cudaFuncAttributeMaxDynamicSharedMemorySize, ATTN_SMEM);
    cudaFuncSetAttribute(attn_B, cudaFuncAttributeMaxDynamicSharedMemorySize, ATTNB_SMEM);
    cudaFuncSetAttribute(proj_h, cudaFuncAttributeMaxDynamicSharedMemorySize, PJ_SMEM);

    xcvt<<<7168, 256>>>(q, k, v, Xin, mask, pmp, Wq, Wk, Wv, Wo, Whp);

    const float qscale = 0.125f * 1.4426950408889634f;
    ProjArgs pq{Xin,               Whp,          bq, Qhp, nullptr, qscale};
    ProjArgs pk{Xin + 2097152,     Whp + 262144, bk, Khp, nullptr, 1.0f};
    ProjArgs pv{Xin + 4194304,     Whp + 524288, bv, Vhp, nullptr, 1.0f};
    proj_h<<<dim3(8, 32, 3), 256, PJ_SMEM>>>(pq, pk, pv);

    vtrans<<<dim3(32, 16), 256>>>(Vhp, Vtp);

    attn_A<<<dim3(32, 16), 512, ATTN_SMEM>>>(Qhp, Khp, Vtp, pmp, rinv, Xhp);

    // Fork: out-projection overlaps attn_B.
    cudaStream_t s2;
    cudaStreamCreate(&s2);
    cudaEvent_t e1, e2;
    cudaEventCreateWithFlags(&e1, cudaEventDisableTiming);
    cudaEventCreateWithFlags(&e2, cudaEventDisableTiming);

    cudaEventRecord(e1, 0);
    cudaStreamWaitEvent(s2, e1, 0);

    ProjArgs po{Xhp, Whp + 786432, bo, nullptr, out, 1.0f};
    proj_h<<<dim3(8, 32, 1), 256, PJ_SMEM, s2>>>(po, po, po);
    cudaEventRecord(e2, s2);

    attn_B<<<dim3(32, 16), 512, ATTNB_SMEM>>>(Qhp, Khp, pmp, rinv, attn);

    cudaStreamWaitEvent(0, e2, 0);
}

// round 17
// speedup vs baseline: 1.0311x; 1.0311x over previous
#include <cuda_runtime.h>
#include <cuda_fp16.h>
#include <math.h>
#include <stdint.h>

#define B_    2
#define S_    2048
#define HID_  512
#define H_    8
#define BH_   16
#define M_    4096

// Scratch (device globals; no allocation allowed)
__device__ __align__(256) __half g_Qh[M_ * HID_];
__device__ __align__(256) __half g_Kh[M_ * HID_];
__device__ __align__(256) __half g_Vh[M_ * HID_];
__device__ __align__(256) __half g_Xh[M_ * HID_];
__device__ __align__(256) __half g_Wh[4 * HID_ * HID_]; // fp16 Wq,Wk,Wv,Wo
__device__ __align__(256) __half g_inx[3 * M_ * HID_];  // fp16 q,k,v inputs
__device__ float g_rowinv[BH_ * S_];
__device__ uint32_t g_pm[M_ * 64];                      // packed mask bits, 1MB
__device__ float g_attn_scratch[(size_t)BH_ * S_ * S_];

// ---------------------------------------------------------------------------
// helpers
// ---------------------------------------------------------------------------
__device__ __forceinline__ unsigned f2h2(float a, float b) {
    __half2 h = __floats2half2_rn(a, b);
    return *(unsigned*)&h;
}

__device__ __forceinline__ float ex2f(float x) {
    float y;
    asm("ex2.approx.f32 %0, %1;" : "=f"(y) : "f"(x));
    return y;
}

__device__ __forceinline__ void mmah(float c[4], const unsigned a[4], const unsigned b[2]) {
    asm volatile(
        "mma.sync.aligned.m16n8k16.row.col.f32.f16.f16.f32 "
        "{%0,%1,%2,%3},{%4,%5,%6,%7},{%8,%9},{%0,%1,%2,%3};"
        : "+f"(c[0]), "+f"(c[1]), "+f"(c[2]), "+f"(c[3])
        : "r"(a[0]), "r"(a[1]), "r"(a[2]), "r"(a[3]),
          "r"(b[0]), "r"(b[1]));
}

__device__ __forceinline__ void ldsm4(uint32_t& r0, uint32_t& r1, uint32_t& r2,
                                      uint32_t& r3, uint32_t a) {
    asm volatile("ldmatrix.sync.aligned.m8n8.x4.shared.b16 {%0,%1,%2,%3}, [%4];"
                 : "=r"(r0), "=r"(r1), "=r"(r2), "=r"(r3) : "r"(a));
}

__device__ __forceinline__ void ldsm4t(uint32_t& r0, uint32_t& r1, uint32_t& r2,
                                       uint32_t& r3, uint32_t a) {
    asm volatile("ldmatrix.sync.aligned.m8n8.x4.trans.shared.b16 {%0,%1,%2,%3}, [%4];"
                 : "=r"(r0), "=r"(r1), "=r"(r2), "=r"(r3) : "r"(a));
}

__device__ __forceinline__ void cp16(uint32_t saddr, const void* g) {
    asm volatile("cp.async.cg.shared.global [%0], [%1], 16;" :: "r"(saddr), "l"(g));
}
__device__ __forceinline__ uint32_t sptr(const void* p) {
    return (uint32_t)__cvta_generic_to_shared(p);
}
__device__ __forceinline__ void stg_cs2(float* p, float a, float b) {
    asm volatile("st.global.cs.v2.f32 [%0], {%1,%2};" :: "l"(p), "f"(a), "f"(b));
}

// ---------------------------------------------------------------------------
// Fused one-time converts: inputs fp32->fp16, mask bit-pack, weights fp32->fp16.
// ---------------------------------------------------------------------------
__global__ void __launch_bounds__(256)
xcvt(const float* __restrict__ q, const float* __restrict__ k,
     const float* __restrict__ v, __half* __restrict__ dst,
     const int* __restrict__ mask, uint32_t* __restrict__ pm,
     const float* __restrict__ Wq, const float* __restrict__ Wk,
     const float* __restrict__ Wv, const float* __restrict__ Wo,
     __half* __restrict__ Wh)
{
    if (blockIdx.x >= 6144) {
        int idx = ((blockIdx.x - 6144) * 256 + threadIdx.x) * 4;
        const float* s = (idx < 262144) ? Wq
                       : (idx < 524288) ? Wk
                       : (idx < 786432) ? Wv : Wo;
        float4 w = *(const float4*)(s + (idx & 262143));
        __half2 h0 = __floats2half2_rn(w.x, w.y);
        __half2 h1 = __floats2half2_rn(w.z, w.w);
        *(uint2*)(Wh + idx) = make_uint2(*(unsigned*)&h0, *(unsigned*)&h1);
        return;
    }

    if (blockIdx.x < 1024) {
        int widx = blockIdx.x * 256 + threadIdx.x;
        const int4* mp = (const int4*)(mask + (size_t)widx * 32);
        uint32_t u = 0;
        #pragma unroll
        for (int j = 0; j < 8; j++) {
            int4 m = __ldg(mp + j);
            u |= (m.x != 0 ? 1u : 0u) << (j * 4);
            u |= (m.y != 0 ? 1u : 0u) << (j * 4 + 1);
            u |= (m.z != 0 ? 1u : 0u) << (j * 4 + 2);
            u |= (m.w != 0 ? 1u : 0u) << (j * 4 + 3);
        }
        pm[widx] = u;
    }

    int idx = (blockIdx.x * 256 + threadIdx.x) * 4;
    const float* s = (idx < 2097152) ? q : (idx < 4194304) ? k : v;
    float4 w = *(const float4*)(s + (idx & 2097151));
    __half2 h0 = __floats2half2_rn(w.x, w.y);
    __half2 h1 = __floats2half2_rn(w.z, w.w);
    *(uint2*)(dst + idx) = make_uint2(*(unsigned*)&h0, *(unsigned*)&h1);
}

// ---------------------------------------------------------------------------
// Unified projection (fp16 X, fp16 W): Y = (X @ W^T + b) * scale
// ---------------------------------------------------------------------------
struct ProjArgs { const __half* X; const __half* W; const float* b;
                  __half* Yh; float* Yf; float scale; };

#define PJ_STAGE 15360
#define PJ_X(s) ((s) * PJ_STAGE)
#define PJ_W(s) ((s) * PJ_STAGE + 10240)
#define PJ_SMEM (3 * PJ_STAGE)

__global__ void __launch_bounds__(256, 3)
proj_h(ProjArgs a0, ProjArgs a1, ProjArgs a2)
{
    const ProjArgs& A_ = (blockIdx.z == 0) ? a0 : (blockIdx.z == 1) ? a1 : a2;
    const __half* __restrict__ Xg = A_.X;
    const __half* __restrict__ Wg = A_.W;
    const float* __restrict__ bias = A_.b;

    extern __shared__ char psm[];
    const uint32_t sb = sptr(psm);

    const int tid = threadIdx.x;
    const int lane = tid & 31, wid = tid >> 5;
    const int g = lane >> 2, tg = lane & 3;
    const int wm = wid & 3, wn = wid >> 2;
    const int m0 = blockIdx.y * 128, n0 = blockIdx.x * 64;

    auto stage = [&](int k0, int s) {
        #pragma unroll
        for (int j = 0; j < 2; j++) {
            int lin = tid + j * 256;
            int r = lin >> 2, c16 = lin & 3;
            cp16(sb + PJ_X(s) + (uint32_t)r * 80u + (uint32_t)c16 * 16u,
                 Xg + (size_t)(m0 + r) * 512 + k0 + c16 * 8);
        }
        {
            int r = tid >> 2, c16 = tid & 3;
            cp16(sb + PJ_W(s) + (uint32_t)r * 80u + (uint32_t)c16 * 16u,
                 Wg + (size_t)(n0 + r) * 512 + k0 + c16 * 8);
        }
        asm volatile("cp.async.commit_group;");
    };

    float acc[2][4][4] = {};

    stage(0, 0);
    stage(32, 1);
    for (int t = 0; t < 16; t++) {
        if (t < 15) asm volatile("cp.async.wait_group 1;");
        else        asm volatile("cp.async.wait_group 0;");
        __syncthreads();
        if (t + 2 < 16) stage((t + 2) * 32, (t + 2) % 3);

        const __half* Xs = (const __half*)(psm + PJ_X(t % 3));
        const __half* Ws = (const __half*)(psm + PJ_W(t % 3));

        #pragma unroll
        for (int ks = 0; ks < 2; ks++) {
            unsigned af[2][4], bf[4][2];
            #pragma unroll
            for (int mi = 0; mi < 2; mi++) {
                const __half* x0 = &Xs[(wm * 32 + mi * 16 + g) * 40 + ks * 16 + 2 * tg];
                const __half* x1 = x0 + 8 * 40;
                af[mi][0] = *(const uint32_t*)x0;
                af[mi][1] = *(const uint32_t*)x1;
                af[mi][2] = *(const uint32_t*)(x0 + 8);
                af[mi][3] = *(const uint32_t*)(x1 + 8);
            }
            #pragma unroll
            for (int ni = 0; ni < 4; ni++) {
                const __half* bb = &Ws[(wn * 32 + ni * 8 + g) * 40 + ks * 16 + 2 * tg];
                bf[ni][0] = *(const uint32_t*)bb;
                bf[ni][1] = *(const uint32_t*)(bb + 8);
            }
            #pragma unroll
            for (int mi = 0; mi < 2; mi++)
                #pragma unroll
                for (int ni = 0; ni < 4; ni++)
                    mmah(acc[mi][ni], af[mi], bf[ni]);
        }
    }

    const float scale = A_.scale;
    #pragma unroll
    for (int mi = 0; mi < 2; mi++) {
        int r0 = m0 + wm * 32 + mi * 16 + g;
        #pragma unroll
        for (int ni = 0; ni < 4; ni++) {
            int c0 = n0 + wn * 32 + ni * 8 + 2 * tg;
            float b0v = __ldg(bias + c0), b1v = __ldg(bias + c0 + 1);
            float y00 = acc[mi][ni][0] + b0v, y01 = acc[mi][ni][1] + b1v;
            float y10 = acc[mi][ni][2] + b0v, y11 = acc[mi][ni][3] + b1v;
            if (A_.Yh) {
                *(unsigned*)(A_.Yh + (size_t)r0 * 512 + c0) = f2h2(y00 * scale, y01 * scale);
                *(unsigned*)(A_.Yh + (size_t)(r0 + 8) * 512 + c0) = f2h2(y10 * scale, y11 * scale);
            } else {
                *(float2*)(A_.Yf + (size_t)r0 * 512 + c0) = make_float2(y00, y01);
                *(float2*)(A_.Yf + (size_t)(r0 + 8) * 512 + c0) = make_float2(y10, y11);
            }
        }
    }
}

// ---------------------------------------------------------------------------
// attn_A: scores+ex2 -> rowsum + PV (register P). ldmatrix fragment feeds;
// V staged as raw rows (same layout as K) and transposed in-register via
// ldmatrix.trans. Outputs rowinv + Xh. No attn write. No vtrans kernel.
// ---------------------------------------------------------------------------
#define SMB_Q    0u
#define SMB_K(s) (9216u + (s) * 18432u)
#define SMB_V(s) (64512u + (s) * 18432u)
#define SMB_RS   119808u
#define ATTN_SMEM (120080 + 16)

__global__ void __launch_bounds__(512, 1)
attn_A(const __half* __restrict__ Qh, const __half* __restrict__ Kh,
       const __half* __restrict__ Vh, const uint32_t* __restrict__ pm,
       float* __restrict__ rowinv, __half* __restrict__ Xo)
{
    extern __shared__ char smg[];
    const uint32_t sb = sptr(smg);

    const int tid = threadIdx.x, lane = tid & 31, w = tid >> 5;
    const int g = lane >> 2, tg = lane & 3;
    const int wm = w & 3, wn = w >> 2;
    const int z = blockIdx.y, strip = blockIdx.x;
    const int bB = z >> 3, h = z & 7;
    const int s0 = strip * 64;

    float* rows = (float*)(smg + SMB_RS);
    if (tid < 64) rows[tid] = 0.f;

    const __half* Qsrc = Qh + (size_t)(bB * S_ + s0) * HID_ + h * 64;
    const __half* Ksrc = Kh + (size_t)(bB * S_) * HID_ + h * 64;
    const __half* Vsrc = Vh + (size_t)(bB * S_) * HID_ + h * 64;

    // scores ldmatrix lane offset (K rows = n)
    const uint32_t so_sc = (uint32_t)(wn * 32 + (lane & 7)) * 144u
                         + ((lane >> 4) & 1) * 32u + ((lane >> 3) & 1) * 16u;
    // PV ldmatrix.trans lane offset (V rows = k/s): lanes 0-7/8-15/16-23/24-31
    // supply s-rows +0..7/+8../+16../+24.. of this warp's 32-k slice.
    const uint32_t so_pv = (uint32_t)(wn * 32 + (lane & 7) + ((lane >> 3) & 3) * 8) * 144u;

    auto loadKV = [&](int chunk, int st) {
        const int kb = chunk * 128;
        #pragma unroll
        for (int j = 0; j < 2; j++) {
            int idx = tid + j * 512;
            int r = idx >> 3, c16 = idx & 7;
            cp16(sb + SMB_K(st) + (uint32_t)r * 144u + (uint32_t)c16 * 16u,
                 Ksrc + (size_t)(kb + r) * HID_ + c16 * 8);
        }
        #pragma unroll
        for (int j = 0; j < 2; j++) {
            int idx = tid + j * 512;
            int r = idx >> 3, c16 = idx & 7;
            cp16(sb + SMB_V(st) + (uint32_t)r * 144u + (uint32_t)c16 * 16u,
                 Vsrc + (size_t)(kb + r) * HID_ + c16 * 8);
        }
        asm volatile("cp.async.commit_group;");
    };

    {
        int r = tid >> 3, c16 = tid & 7;
        cp16(sb + SMB_Q + (uint32_t)r * 144u + (uint32_t)c16 * 16u,
             Qsrc + (size_t)r * HID_ + c16 * 8);
    }
    loadKV(0, 0);
    loadKV(1, 1);
    asm volatile("cp.async.wait_group 1;");
    __syncthreads();

    const __half* Qs = (const __half*)(smg + SMB_Q);
    unsigned qa[4][4];
    #pragma unroll
    for (int ks = 0; ks < 4; ks++) {
        const __half* qr0 = Qs + (wm * 16 + g) * 72 + ks * 16 + 2 * tg;
        const __half* qr1 = qr0 + 8 * 72;
        qa[ks][0] = *(const uint32_t*)qr0;
        qa[ks][1] = *(const uint32_t*)qr1;
        qa[ks][2] = *(const uint32_t*)(qr0 + 8);
        qa[ks][3] = *(const uint32_t*)(qr1 + 8);
    }

    float pvacc[8][4] = {};
    float rsA = 0.f, rsB = 0.f;

    const int rA = bB * S_ + s0 + wm * 16 + g;

    for (int it = 0; it < 16; it++) {
        const int st = it % 3;

        const uint32_t wa = __ldg(pm + (uint32_t)rA * 64u + it * 4 + wn);
        const uint32_t wb = __ldg(pm + (uint32_t)(rA + 8) * 64u + it * 4 + wn);

        if (it > 0) {
            if (it < 15) asm volatile("cp.async.wait_group 1;");
            else         asm volatile("cp.async.wait_group 0;");
            __syncthreads();
        }
        if (it + 2 < 16) loadKV(it + 2, (it + 2) % 3);

        float c[4][4] = {};
        {
            const uint32_t kbase = sb + SMB_K(st) + so_sc;
            #pragma unroll
            for (int p = 0; p < 2; p++) {
                #pragma unroll
                for (int nt = 0; nt < 4; nt++) {
                    uint32_t r0, r1, r2, r3;
                    ldsm4(r0, r1, r2, r3, kbase + (uint32_t)nt * 1152u + (uint32_t)p * 64u);
                    unsigned b0[2] = { r0, r1 }, b1[2] = { r2, r3 };
                    mmah(c[nt], qa[2 * p], b0);
                    mmah(c[nt], qa[2 * p + 1], b1);
                }
            }
        }

        float p[4][4];
        #pragma unroll
        for (int nt = 0; nt < 4; nt++) {
            p[nt][0] = ex2f(c[nt][0]);
            p[nt][1] = ex2f(c[nt][1]);
            p[nt][2] = ex2f(c[nt][2]);
            p[nt][3] = ex2f(c[nt][3]);
        }
        if ((wa & wb) != 0xFFFFFFFFu) {
            #pragma unroll
            for (int nt = 0; nt < 4; nt++) {
                int sh = nt * 8 + 2 * tg;
                if (!((wa >> sh) & 1u))       p[nt][0] = 0.f;
                if (!((wa >> (sh + 1)) & 1u)) p[nt][1] = 0.f;
                if (!((wb >> sh) & 1u))       p[nt][2] = 0.f;
                if (!((wb >> (sh + 1)) & 1u)) p[nt][3] = 0.f;
            }
        }
        #pragma unroll
        for (int nt = 0; nt < 4; nt++) {
            rsA += p[nt][0] + p[nt][1];
            rsB += p[nt][2] + p[nt][3];
        }

        unsigned pa[2][4];
        #pragma unroll
        for (int k2 = 0; k2 < 2; k2++) {
            pa[k2][0] = f2h2(p[2 * k2][0], p[2 * k2][1]);
            pa[k2][1] = f2h2(p[2 * k2][2], p[2 * k2][3]);
            pa[k2][2] = f2h2(p[2 * k2 + 1][0], p[2 * k2 + 1][1]);
            pa[k2][3] = f2h2(p[2 * k2 + 1][2], p[2 * k2 + 1][3]);
        }

        // PV: V rows in smem, transposed in-register (8 ldsm.trans x4)
        {
            const uint32_t vbase = sb + SMB_V(st) + so_pv;
            #pragma unroll
            for (int nt2 = 0; nt2 < 8; nt2++) {
                uint32_t r0, r1, r2, r3;
                ldsm4t(r0, r1, r2, r3, vbase + (uint32_t)nt2 * 16u);
                unsigned b0[2] = { r0, r1 }, b1[2] = { r2, r3 };
                mmah(pvacc[nt2], pa[0], b0);
                mmah(pvacc[nt2], pa[1], b1);
            }
        }
    }

    rsA += __shfl_xor_sync(0xffffffffu, rsA, 1);
    rsA += __shfl_xor_sync(0xffffffffu, rsA, 2);
    rsB += __shfl_xor_sync(0xffffffffu, rsB, 1);
    rsB += __shfl_xor_sync(0xffffffffu, rsB, 2);
    if (tg == 0) {
        atomicAdd(&rows[wm * 16 + g    ], rsA);
        atomicAdd(&rows[wm * 16 + g + 8], rsB);
    }
    __syncthreads();

    if (tid < 64) {
        float inv = 1.0f / rows[tid];
        rows[tid] = inv;
        rowinv[(size_t)z * S_ + s0 + tid] = inv;
    }

    const uint32_t scrOff[4] = { SMB_V(0), SMB_V(1), SMB_V(2), SMB_K(2) };
    {
        float* sw = (float*)(smg + scrOff[wn]);
        #pragma unroll
        for (int nt2 = 0; nt2 < 8; nt2++) {
            int col = nt2 * 8 + 2 * tg;
            *(float2*)&sw[(wm * 16 + g    ) * 64 + col] =
                make_float2(pvacc[nt2][0], pvacc[nt2][1]);
            *(float2*)&sw[(wm * 16 + g + 8) * 64 + col] =
                make_float2(pvacc[nt2][2], pvacc[nt2][3]);
        }
    }
    __syncthreads();

    {
        int r = tid >> 3, cg = (tid & 7) * 8;
        float4 s0v = make_float4(0, 0, 0, 0), s1v = make_float4(0, 0, 0, 0);
        #pragma unroll
        for (int ww = 0; ww < 4; ww++) {
            const float* sw = (const float*)(smg + scrOff[ww]);
            float4 u0 = *(const float4*)&sw[r * 64 + cg];
            float4 u1 = *(const float4*)&sw[r * 64 + cg + 4];
            s0v.x += u0.x; s0v.y += u0.y; s0v.z += u0.z; s0v.w += u0.w;
            s1v.x += u1.x; s1v.y += u1.y; s1v.z += u1.z; s1v.w += u1.w;
        }
        float inv = rows[r];
        uint4 ov;
        ov.x = f2h2(s0v.x * inv, s0v.y * inv);
        ov.y = f2h2(s0v.z * inv, s0v.w * inv);
        ov.z = f2h2(s1v.x * inv, s1v.y * inv);
        ov.w = f2h2(s1v.z * inv, s1v.w * inv);
        *(uint4*)(Xo + (size_t)(bB * S_ + s0 + r) * HID_ + h * 64 + cg) = ov;
    }
}

// ---------------------------------------------------------------------------
// attn_B: recompute scores (ldmatrix feeds), ex2, pm fast path + inv rowsum,
// evict-first attn stores. 64-row q-tile, 512 thr, 2 CTAs/SM.
// ---------------------------------------------------------------------------
#define BB_Q    0u
#define BB_K(s) (9216u + (s) * 18432u)
#define ATTNB_SMEM (9216 + 3 * 18432 + 16)

__global__ void __launch_bounds__(512, 2)
attn_B(const __half* __restrict__ Qh, const __half* __restrict__ Kh,
       const uint32_t* __restrict__ pm, const float* __restrict__ rowinv,
       float* __restrict__ attn)
{
    extern __shared__ char smg[];
    const uint32_t sb = sptr(smg);

    const int tid = threadIdx.x, lane = tid & 31, w = tid >> 5;
    const int g = lane >> 2, tg = lane & 3;
    const int wm = w & 3, wn = w >> 2;
    const int z = blockIdx.y, strip = blockIdx.x;
    const int bB = z >> 3, h = z & 7;
    const int s0 = strip * 64;

    const __half* Qsrc = Qh + (size_t)(bB * S_ + s0) * HID_ + h * 64;
    const __half* Ksrc = Kh + (size_t)(bB * S_) * HID_ + h * 64;

    const uint32_t so_sc = (uint32_t)(wn * 32 + (lane & 7)) * 144u
                         + ((lane >> 4) & 1) * 32u + ((lane >> 3) & 1) * 16u;

    auto loadK = [&](int chunk, int st) {
        const int kb = chunk * 128;
        #pragma unroll
        for (int j = 0; j < 2; j++) {
            int idx = tid + j * 512;
            int r = idx >> 3, c16 = idx & 7;
            cp16(sb + BB_K(st) + (uint32_t)r * 144u + (uint32_t)c16 * 16u,
                 Ksrc + (size_t)(kb + r) * HID_ + c16 * 8);
        }
        asm volatile("cp.async.commit_group;");
    };

    {
        int r = tid >> 3, c16 = tid & 7;
        cp16(sb + BB_Q + (uint32_t)r * 144u + (uint32_t)c16 * 16u,
             Qsrc + (size_t)r * HID_ + c16 * 8);
    }
    loadK(0, 0);
    loadK(1, 1);
    asm volatile("cp.async.wait_group 1;");
    __syncthreads();

    const __half* Qs = (const __half*)(smg + BB_Q);
    unsigned qa[4][4];
    #pragma unroll
    for (int ks = 0; ks < 4; ks++) {
        const __half* qr0 = Qs + (wm * 16 + g) * 72 + ks * 16 + 2 * tg;
        const __half* qr1 = qr0 + 8 * 72;
        qa[ks][0] = *(const uint32_t*)qr0;
        qa[ks][1] = *(const uint32_t*)qr1;
        qa[ks][2] = *(const uint32_t*)(qr0 + 8);
        qa[ks][3] = *(const uint32_t*)(qr1 + 8);
    }

    const int rowA = s0 + wm * 16 + g;
    const int rA = bB * S_ + rowA;
    const float invA = __ldg(rowinv + (size_t)z * S_ + rowA);
    const float invB = __ldg(rowinv + (size_t)z * S_ + rowA + 8);
    const size_t arowA = ((size_t)z * S_ + rowA) * S_;
    const size_t arowB = arowA + 8 * S_;

    for (int it = 0; it < 16; it++) {
        const int kb = it * 128;
        const int st = it % 3;

        const uint32_t wa = __ldg(pm + (uint32_t)rA * 64u + it * 4 + wn);
        const uint32_t wb = __ldg(pm + (uint32_t)(rA + 8) * 64u + it * 4 + wn);

        if (it > 0) {
            if (it < 15) asm volatile("cp.async.wait_group 1;");
            else         asm volatile("cp.async.wait_group 0;");
            __syncthreads();
        }
        if (it + 2 < 16) loadK(it + 2, (it + 2) % 3);

        float c[4][4] = {};
        {
            const uint32_t kbase = sb + BB_K(st) + so_sc;
            #pragma unroll
            for (int p = 0; p < 2; p++) {
                #pragma unroll
                for (int nt = 0; nt < 4; nt++) {
                    uint32_t r0, r1, r2, r3;
                    ldsm4(r0, r1, r2, r3, kbase + (uint32_t)nt * 1152u + (uint32_t)p * 64u);
                    unsigned b0[2] = { r0, r1 }, b1[2] = { r2, r3 };
                    mmah(c[nt], qa[2 * p], b0);
                    mmah(c[nt], qa[2 * p + 1], b1);
                }
            }
        }

        float p[4][4];
        #pragma unroll
        for (int nt = 0; nt < 4; nt++) {
            p[nt][0] = ex2f(c[nt][0]) * invA;
            p[nt][1] = ex2f(c[nt][1]) * invA;
            p[nt][2] = ex2f(c[nt][2]) * invB;
            p[nt][3] = ex2f(c[nt][3]) * invB;
        }
        if ((wa & wb) != 0xFFFFFFFFu) {
            #pragma unroll
            for (int nt = 0; nt < 4; nt++) {
                int sh = nt * 8 + 2 * tg;
                if (!((wa >> sh) & 1u))       p[nt][0] = 0.f;
                if (!((wa >> (sh + 1)) & 1u)) p[nt][1] = 0.f;
                if (!((wb >> sh) & 1u))       p[nt][2] = 0.f;
                if (!((wb >> (sh + 1)) & 1u)) p[nt][3] = 0.f;
            }
        }
        #pragma unroll
        for (int nt = 0; nt < 4; nt++) {
            int cg = kb + wn * 32 + nt * 8 + 2 * tg;
            stg_cs2(attn + arowA + cg, p[nt][0], p[nt][1]);
            stg_cs2(attn + arowB + cg, p[nt][2], p[nt][3]);
        }
    }
}

// ---------------------------------------------------------------------------
// Launch
// ---------------------------------------------------------------------------
extern "C" void kernel_launch(void* const* d_in, const int* in_sizes, int n_in,
                              void* d_out, int out_size)
{
    const float* q    = (const float*)d_in[0];
    const float* k    = (const float*)d_in[1];
    const float* v    = (const float*)d_in[2];
    const int*   mask = (const int*)  d_in[3];
    const float* Wq   = (const float*)d_in[4];
    const float* bq   = (const float*)d_in[5];
    const float* Wk   = (const float*)d_in[6];
    const float* bk   = (const float*)d_in[7];
    const float* Wv   = (const float*)d_in[8];
    const float* bv   = (const float*)d_in[9];
    const float* Wo   = (const float*)d_in[10];
    const float* bo   = (const float*)d_in[11];

    float* out = (float*)d_out;

    __half *Qhp, *Khp, *Vhp, *Xhp, *Whp, *Xin;
    float *rinv, *scr;
    uint32_t* pmp;
    cudaGetSymbolAddress((void**)&Qhp, g_Qh);
    cudaGetSymbolAddress((void**)&Khp, g_Kh);
    cudaGetSymbolAddress((void**)&Vhp, g_Vh);
    cudaGetSymbolAddress((void**)&Xhp, g_Xh);
    cudaGetSymbolAddress((void**)&Whp, g_Wh);
    cudaGetSymbolAddress((void**)&Xin, g_inx);
    cudaGetSymbolAddress((void**)&rinv, g_rowinv);
    cudaGetSymbolAddress((void**)&pmp, g_pm);
    cudaGetSymbolAddress((void**)&scr, g_attn_scratch);

    const size_t out_elems  = (size_t)M_ * HID_;
    const size_t attn_elems = (size_t)BH_ * S_ * S_;
    float* attn = ((size_t)out_size >= out_elems + attn_elems) ? out + out_elems : scr;

    cudaFuncSetAttribute(attn_A, cudaFuncAttributeMaxDynamicSharedMemorySize, ATTN_SMEM);
    cudaFuncSetAttribute(attn_B, cudaFuncAttributeMaxDynamicSharedMemorySize, ATTNB_SMEM);
    cudaFuncSetAttribute(proj_h, cudaFuncAttributeMaxDynamicSharedMemorySize, PJ_SMEM);

    xcvt<<<7168, 256>>>(q, k, v, Xin, mask, pmp, Wq, Wk, Wv, Wo, Whp);

    const float qscale = 0.125f * 1.4426950408889634f;
    ProjArgs pq{Xin,               Whp,          bq, Qhp, nullptr, qscale};
    ProjArgs pk{Xin + 2097152,     Whp + 262144, bk, Khp, nullptr, 1.0f};
    ProjArgs pv{Xin + 4194304,     Whp + 524288, bv, Vhp, nullptr, 1.0f};
    proj_h<<<dim3(8, 32, 3), 256, PJ_SMEM>>>(pq, pk, pv);

    attn_A<<<dim3(32, 16), 512, ATTN_SMEM>>>(Qhp, Khp, Vhp, pmp, rinv, Xhp);

    // Fork: out-projection overlaps attn_B.
    cudaStream_t s2;
    cudaStreamCreate(&s2);
    cudaEvent_t e1, e2;
    cudaEventCreateWithFlags(&e1, cudaEventDisableTiming);
    cudaEventCreateWithFlags(&e2, cudaEventDisableTiming);

    cudaEventRecord(e1, 0);
    cudaStreamWaitEvent(s2, e1, 0);

    ProjArgs po{Xhp, Whp + 786432, bo, nullptr, out, 1.0f};
    proj_h<<<dim3(8, 32, 1), 256, PJ_SMEM, s2>>>(po, po, po);
    cudaEventRecord(e2, s2);

    attn_B<<<dim3(32, 16), 512, ATTNB_SMEM>>>(Qhp, Khp, pmp, rinv, attn);

    cudaStreamWaitEvent(0, e2, 0);
}